// round 9
// baseline (speedup 1.0000x reference)
#include <cuda_runtime.h>
#include <math.h>
#include <stdint.h>

#define N_FEAT 7
#define FUZZ   2187
#define PADJ   2188          // FUZZ padded to multiple of 4 floats
#define NVJ    547           // PADJ/4 vec4 columns
#define MID    512
#define NCLS   10
#define BATCH  4096
#define T21    21
#define NCHUNK 81            // chunks of 27 k
#define CHUNK_K 27
#define NSLOT  13            // f0..f3 scalar + 3x3 for f4..f6
#define WCH    16
#define COLT   9             // 256-wide column tiles (fold/partF)
#define NROWS  15309
#define TOTAL  ((size_t)NROWS * FUZZ)   // 33,480,783 floats in wei

// ---- device scratch (no allocations allowed) ----
__device__ __align__(16) float g_p[(size_t)NCHUNK * NSLOT * PADJ];  // 9.2 MB
__device__ __align__(16) float g_S[T21 * PADJ];
__device__ float g_rowS[T21];
__device__ float g_partW[WCH * NCLS * MID];
__device__ float g_W23[NCLS * MID];
__device__ float g_partF[NCLS * COLT * 24];

__device__ __forceinline__ void fadd4(float4& a, float4 v) {
    a.x += v.x; a.y += v.y; a.z += v.z; a.w += v.w;
}
__device__ __forceinline__ void ffma4(float4& a, float m, float4 v) {
    a.x += m * v.x; a.y += m * v.y; a.z += m * v.z; a.w += m * v.w;
}

// Load 4 columns [4G..4G+3] of the row at rowbase, whose base is misaligned
// by S floats (S = (3*r)&3, compile-time). Aligned LDG.128 + lane shuffle
// recovers the window; the buffer tail uses guarded scalar loads (ae is
// always 16B-aligned by construction: rowbase % 4 == S).
template<int S>
__device__ __forceinline__ float4 ldrow(const float* __restrict__ wei,
                                        size_t rowbase, int G, int lane) {
    size_t ae = rowbase + (size_t)(4 * G) - (size_t)S;
    float4 o;
    if (ae + 4 <= TOTAL) {
        o = __ldg((const float4*)(wei + ae));
    } else {
        o.x = (ae + 0 < TOTAL) ? __ldg(wei + ae + 0) : 0.f;
        o.y = (ae + 1 < TOTAL) ? __ldg(wei + ae + 1) : 0.f;
        o.z = (ae + 2 < TOTAL) ? __ldg(wei + ae + 2) : 0.f;
        o.w = (ae + 3 < TOTAL) ? __ldg(wei + ae + 3) : 0.f;
    }
    if (S == 0) return o;
    float n0 = __shfl_down_sync(0xffffffffu, o.x, 1);
    float n1 = (S >= 2) ? __shfl_down_sync(0xffffffffu, o.y, 1) : 0.f;
    float n2 = (S >= 3) ? __shfl_down_sync(0xffffffffu, o.z, 1) : 0.f;
    if (lane == 31) {
        size_t ae2 = ae + 4;
        if (ae2 + 4 <= TOTAL) {
            float4 ex = __ldg((const float4*)(wei + ae2));
            n0 = ex.x; n1 = ex.y; n2 = ex.z;
        } else {
            n0 = (ae2 + 0 < TOTAL) ? __ldg(wei + ae2 + 0) : 0.f;
            n1 = (ae2 + 1 < TOTAL) ? __ldg(wei + ae2 + 1) : 0.f;
            n2 = (ae2 + 2 < TOTAL) ? __ldg(wei + ae2 + 2) : 0.f;
        }
    }
    float4 r;
    if (S == 1)      { r.x = o.y; r.y = o.z; r.z = o.w; r.w = n0; }
    else if (S == 2) { r.x = o.z; r.y = o.w; r.z = n0;  r.w = n1; }
    else             { r.x = o.w; r.y = n0;  r.z = n1;  r.w = n2; }
    return r;
}

// One k-group (7 rows, f=0..6). S0 = alignment shift of row f=0 (compile-time).
template<int S0>
__device__ __forceinline__ void kgroup(const float* __restrict__ wei,
                                       size_t rb, int G, int lane,
                                       float4* a, const float* msk) {
    fadd4(a[0], ldrow<(S0 + 0) & 3>(wei, rb + 0 * (size_t)FUZZ, G, lane));
    fadd4(a[1], ldrow<(S0 + 3) & 3>(wei, rb + 1 * (size_t)FUZZ, G, lane));
    fadd4(a[2], ldrow<(S0 + 6) & 3>(wei, rb + 2 * (size_t)FUZZ, G, lane));
    fadd4(a[3], ldrow<(S0 + 9) & 3>(wei, rb + 3 * (size_t)FUZZ, G, lane));
    {
        float4 v = ldrow<(S0 + 12) & 3>(wei, rb + 4 * (size_t)FUZZ, G, lane);
        ffma4(a[4], msk[0], v); ffma4(a[5], msk[1], v); ffma4(a[6], msk[2], v);
    }
    {
        float4 v = ldrow<(S0 + 15) & 3>(wei, rb + 5 * (size_t)FUZZ, G, lane);
        ffma4(a[7], msk[3], v); ffma4(a[8], msk[4], v); ffma4(a[9], msk[5], v);
    }
    {
        float4 v = ldrow<(S0 + 18) & 3>(wei, rb + 6 * (size_t)FUZZ, G, lane);
        ffma4(a[10], msk[6], v); ffma4(a[11], msk[7], v); ffma4(a[12], msk[8], v);
    }
}

// ============================================================
// Stage 1 (vec4): compact 13-slot S partials, 243 blocks.
// ============================================================
__global__ void __launch_bounds__(256) k_stage1v(const float* __restrict__ wei) {
    int tid  = threadIdx.x;
    int lane = tid & 31;
    int chunk = blockIdx.x / 3;
    int ct    = blockIdx.x % 3;
    int G = ct * 256 + tid;          // vec-col index: columns 4G..4G+3

    float4 a[NSLOT];
#pragma unroll
    for (int s = 0; s < NSLOT; s++) a[s] = make_float4(0.f, 0.f, 0.f, 0.f);

    int r0 = chunk * 189;            // rows contiguous: r = r0 + kk*7 + f
    for (int kk = 0; kk < CHUNK_K; kk++) {
        int m4 = kk / 9, m5 = (kk / 3) % 3, m6 = kk % 3;
        float msk[9] = {
            m4 == 0 ? 1.f : 0.f, m4 == 1 ? 1.f : 0.f, m4 == 2 ? 1.f : 0.f,
            m5 == 0 ? 1.f : 0.f, m5 == 1 ? 1.f : 0.f, m5 == 2 ? 1.f : 0.f,
            m6 == 0 ? 1.f : 0.f, m6 == 1 ? 1.f : 0.f, m6 == 2 ? 1.f : 0.f };
        int r = r0 + kk * 7;
        size_t rb = (size_t)r * FUZZ;
        switch ((3 * r) & 3) {       // block-uniform
            case 0: kgroup<0>(wei, rb, G, lane, a, msk); break;
            case 1: kgroup<1>(wei, rb, G, lane, a, msk); break;
            case 2: kgroup<2>(wei, rb, G, lane, a, msk); break;
            default: kgroup<3>(wei, rb, G, lane, a, msk); break;
        }
    }

    if (G <= 546) {                  // covers all 2187 real columns (+1 pad)
        float* dst = g_p + (size_t)chunk * NSLOT * PADJ + 4 * G;
#pragma unroll
        for (int s = 0; s < NSLOT; s++)
            *(float4*)(dst + (size_t)s * PADJ) = a[s];
    }
}

// ============================================================
// W23 partials (two tiny launches) + reduce
// ============================================================
__global__ void k_w23part(const float* __restrict__ W2,
                          const float* __restrict__ W3, int cofs) {
    int b = blockIdx.x + cofs;       // 0..31
    int tid = threadIdx.x;
    int itile = b & 1, chunk = b >> 1;
    int i  = itile * 256 + tid;
    int j0 = chunk * 137;
    int j1 = min(FUZZ, j0 + 137);

    float acc[NCLS];
#pragma unroll
    for (int n = 0; n < NCLS; n++) acc[n] = 0.f;
    for (int j = j0; j < j1; j++) {
        float w2 = __ldg(W2 + j * MID + i);
#pragma unroll
        for (int n = 0; n < NCLS; n++)
            acc[n] += __ldg(W3 + n * FUZZ + j) * w2;
    }
#pragma unroll
    for (int n = 0; n < NCLS; n++)
        g_partW[chunk * (NCLS * MID) + n * MID + i] = acc[n];
}

__global__ void k_w23red() {
    int e = blockIdx.x * 256 + threadIdx.x;
    if (e < NCLS * MID) {
        float s = 0.f;
#pragma unroll
        for (int c = 0; c < WCH; c++) s += g_partW[c * (NCLS * MID) + e];
        g_W23[e] = s;
    }
}

// ============================================================
// Stage 2: reduce compact partials -> padded S (vec4, fixed order)
// ============================================================
__global__ void k_reduceS() {
    int vt = blockIdx.x * 256 + threadIdx.x;
    if (vt >= T21 * NVJ) return;
    int t = vt / NVJ, G = vt % NVJ;
    int f = t / 3, m = t % 3;

    float4 s = make_float4(0.f, 0.f, 0.f, 0.f);
    if (f < 4) {
        const int Dt[4] = {27, 9, 3, 1};
        int D = Dt[f], n3D = 3 * D;
        for (int hi = 0; hi < NCHUNK / n3D; hi++)
            for (int lo = 0; lo < D; lo++) {
                int c = hi * n3D + m * D + lo;
                fadd4(s, *(const float4*)&g_p[((size_t)c * NSLOT + f) * PADJ + 4 * G]);
            }
    } else {
        int slot = 4 + (f - 4) * 3 + m;
        const float* p = g_p + (size_t)slot * PADJ + 4 * G;
#pragma unroll 3
        for (int c = 0; c < NCHUNK; c++)
            fadd4(s, *(const float4*)(p + (size_t)c * NSLOT * PADJ));
    }
    *(float4*)&g_S[t * PADJ + 4 * G] = s;
}

// ============================================================
// Stage 3: fold. V = W3 + W23*W1; per (n,jtile): G/q/cc2 partials;
//   last T21 blocks: rowS.
// ============================================================
__global__ void __launch_bounds__(256) k_fold(const float* __restrict__ W1,
                                              const float* __restrict__ W3,
                                              const float* __restrict__ b1,
                                              const float* __restrict__ b2,
                                              const float* __restrict__ b3) {
    int b = blockIdx.x, tid = threadIdx.x, lane = tid & 31, warp = tid >> 5;

    if (b < NCLS * COLT) {
        __shared__ float sW[MID];
        __shared__ float sV[256];
        int n = b / COLT, jt = b % COLT;

        for (int i = tid; i < MID; i += 256) sW[i] = g_W23[n * MID + i];
        __syncthreads();

        int j = jt * 256 + tid;
        bool jok = (j < FUZZ);
        int jj = jok ? j : (FUZZ - 1);

        float V = __ldg(W3 + n * FUZZ + jj);
        const float* wp = W1 + jj;
#pragma unroll 8
        for (int i = 0; i < MID; i++)
            V += sW[i] * __ldg(wp + (size_t)i * FUZZ);
        sV[tid] = jok ? V : 0.f;
        __syncthreads();

        float* dst = g_partF + (n * COLT + jt) * 24;
        int j0 = jt * 256;
        for (int t = warp; t < 24; t += 8) {
            float s = 0.f;
            if (t < T21) {
#pragma unroll
                for (int c = 0; c < 8; c++) {
                    int idx = c * 32 + lane;
                    int jx = j0 + idx;
                    float Sv = (jx < FUZZ) ? __ldg(&g_S[t * PADJ + jx]) : 0.f;
                    s += sV[idx] * Sv;
                }
            } else if (t == 21) {
#pragma unroll
                for (int c = 0; c < 8; c++) s += sV[c * 32 + lane];
            } else if (t == 22) {
#pragma unroll
                for (int c = 0; c < 8; c++) {
                    int jx = j0 + c * 32 + lane;
                    if (jx < FUZZ)
                        s += __ldg(W3 + n * FUZZ + jx) * __ldg(b2 + jx);
                }
            } else { // t == 23: only jt==0 adds b3 + W23.b1
                if (jt == 0) {
#pragma unroll
                    for (int c = 0; c < MID / 32; c++)
                        s += sW[c * 32 + lane] * __ldg(b1 + c * 32 + lane);
                }
            }
            for (int o = 16; o; o >>= 1)
                s += __shfl_down_sync(0xffffffffu, s, o);
            if (lane == 0) {
                if (t == 23 && jt == 0) s += __ldg(b3 + n);
                dst[t] = s;
            }
        }
    } else {
        __shared__ float sred[8];
        int t = b - NCLS * COLT;
        float s = 0.f;
        for (int j = tid; j < FUZZ; j += 256) s += g_S[t * PADJ + j];
        for (int o = 16; o; o >>= 1)
            s += __shfl_down_sync(0xffffffffu, s, o);
        if (lane == 0) sred[warp] = s;
        __syncthreads();
        if (tid == 0) {
            float tot = 0.f;
#pragma unroll
            for (int w = 0; w < 8; w++) tot += sred[w];
            g_rowS[t] = tot;
        }
    }
}

// ============================================================
// Stage 4: assemble partials, one thread per batch row
// ============================================================
__global__ void __launch_bounds__(256) k_main(
        const float* __restrict__ x,  const float* __restrict__ cc,
        const float* __restrict__ bb, const float* __restrict__ bais,
        float* __restrict__ out) {
    __shared__ float sG[NCLS * T21];
    __shared__ float sq[NCLS];
    __shared__ float scc[NCLS];
    __shared__ float srowS[T21];
    __shared__ float sc[T21];
    __shared__ float sib[T21];

    int tid = threadIdx.x;
    for (int e = tid; e < NCLS * T21; e += 256) {
        int n = e / T21, t = e % T21;
        float s = 0.f;
#pragma unroll
        for (int jt = 0; jt < COLT; jt++)
            s += g_partF[(n * COLT + jt) * 24 + t];
        sG[e] = s;
    }
    if (tid < NCLS) {
        float qq = 0.f, cv = 0.f;
#pragma unroll
        for (int jt = 0; jt < COLT; jt++) {
            qq += g_partF[(tid * COLT + jt) * 24 + 21];
            cv += g_partF[(tid * COLT + jt) * 24 + 22]
                + g_partF[(tid * COLT + jt) * 24 + 23];
        }
        sq[tid] = qq;
        scc[tid] = cv;
    }
    if (tid < T21) {
        srowS[tid] = g_rowS[tid];
        sc[tid] = __ldg(cc + tid);
        float bw = __ldg(bb + tid);
        sib[tid] = 1.0f / (bw * bw);
    }
    float bv = __ldg(bais);
    __syncthreads();

    int row = blockIdx.x * 256 + tid;
    float xv[N_FEAT];
#pragma unroll
    for (int f = 0; f < N_FEAT; f++) xv[f] = __ldg(x + row * N_FEAT + f);

    float u[T21];
    float rs = (float)FUZZ * bv;
#pragma unroll
    for (int t = 0; t < T21; t++) {
        float d = xv[t / 3] - sc[t];
        u[t] = expf(-d * d * sib[t]);
        rs += u[t] * srowS[t];
    }
    float inv = 1.0f / rs;

#pragma unroll
    for (int n = 0; n < NCLS; n++) {
        float s = bv * sq[n];
#pragma unroll
        for (int t = 0; t < T21; t++) s += u[t] * sG[n * T21 + t];
        float h = inv * s + scc[n];
        out[row * NCLS + n] = (h >= 0.f) ? h : 0.2f * h;
    }
}

// ============================================================
extern "C" void kernel_launch(void* const* d_in, const int* in_sizes, int n_in,
                              void* d_out, int out_size) {
    const float* x    = (const float*)d_in[0];
    const float* c    = (const float*)d_in[1];
    const float* b    = (const float*)d_in[2];
    const float* wei  = (const float*)d_in[3];
    const float* bais = (const float*)d_in[4];
    const float* W1   = (const float*)d_in[5];
    const float* b1   = (const float*)d_in[6];
    const float* W2   = (const float*)d_in[7];
    const float* b2   = (const float*)d_in[8];
    const float* W3   = (const float*)d_in[9];
    const float* b3   = (const float*)d_in[10];
    float* out = (float*)d_out;

    k_w23part<<<16, 256>>>(W2, W3, 0);      // pos 1
    k_w23part<<<16, 256>>>(W2, W3, 16);     // pos 2
    k_w23red<<<20, 256>>>();                // pos 3
    k_stage1v<<<243, 256>>>(wei);           // pos 4  <- profiled window
    k_reduceS<<<45, 256>>>();               // pos 5
    k_fold<<<NCLS * COLT + T21, 256>>>(W1, W3, b1, b2, b3);  // pos 6
    k_main<<<BATCH / 256, 256>>>(x, c, b, bais, out);        // pos 7
}

// round 10
// speedup vs baseline: 1.8382x; 1.8382x over previous
#include <cuda_runtime.h>
#include <math.h>

#define N_FEAT 7
#define FUZZ   2187
#define MID    512
#define NCLS   10
#define BATCH  4096
#define T21    21
#define CHUNK_K 9
#define NCHUNK  243          // 243*9 = 2187 k's
#define NSLOT   11           // f0..f4 scalar + 3 for f5 + 3 for f6
#define COLT    9            // 256-wide column tiles
#define WCH     16           // j-chunks for W23 partials

// ---- device scratch (no allocations allowed) ----
__device__ float g_p[(size_t)NCHUNK * NSLOT * FUZZ];   // 23.4 MB
__device__ float g_S[T21 * FUZZ];
__device__ float g_rowS[T21];
__device__ float g_partW[WCH * NCLS * MID];
__device__ float g_W23[NCLS * MID];
__device__ float g_partF[NCLS * COLT * 24];

// ============================================================
// Stage 1: 2187 S-blocks (chunk of 9 k's x 256-col tile) + 32 W23 blocks.
//   k = chunk*9 + q. digits f0..f4 are block-constant (scalar acc);
//   f5 = (q/3)%3, f6 = q%3 compile-time under full unroll -> 1 FADD/load.
// ============================================================
__global__ void __launch_bounds__(256) k_stage1(
        const float* __restrict__ wei,
        const float* __restrict__ W2,
        const float* __restrict__ W3) {
    int b   = blockIdx.x;
    int tid = threadIdx.x;

    if (b < NCHUNK * COLT) {
        int colTile = b % COLT;
        int chunk   = b / COLT;
        int j  = colTile * 256 + tid;
        bool ok = (j < FUZZ);
        int jj = ok ? j : 0;

        float s0 = 0.f, s1 = 0.f, s2 = 0.f, s3 = 0.f, s4 = 0.f;
        float a50 = 0.f, a51 = 0.f, a52 = 0.f;
        float a60 = 0.f, a61 = 0.f, a62 = 0.f;

        const float* base = wei + (size_t)(chunk * 63) * FUZZ + jj;
#pragma unroll
        for (int q = 0; q < CHUNK_K; q++) {
            const float* rp = base + (size_t)(q * 7) * FUZZ;
            s0 += __ldg(rp + 0 * FUZZ);
            s1 += __ldg(rp + 1 * FUZZ);
            s2 += __ldg(rp + 2 * FUZZ);
            s3 += __ldg(rp + 3 * FUZZ);
            s4 += __ldg(rp + 4 * FUZZ);
            float v5 = __ldg(rp + 5 * FUZZ);
            float v6 = __ldg(rp + 6 * FUZZ);
            if (q / 3 == 0) a50 += v5; else if (q / 3 == 1) a51 += v5; else a52 += v5;
            if (q % 3 == 0) a60 += v6; else if (q % 3 == 1) a61 += v6; else a62 += v6;
        }
        if (ok) {
            float* dst = g_p + (size_t)chunk * (NSLOT * FUZZ) + j;
            dst[0 * FUZZ]  = s0;
            dst[1 * FUZZ]  = s1;
            dst[2 * FUZZ]  = s2;
            dst[3 * FUZZ]  = s3;
            dst[4 * FUZZ]  = s4;
            dst[5 * FUZZ]  = a50;
            dst[6 * FUZZ]  = a51;
            dst[7 * FUZZ]  = a52;
            dst[8 * FUZZ]  = a60;
            dst[9 * FUZZ]  = a61;
            dst[10 * FUZZ] = a62;
        }
    } else {
        // ---- W23 partial: W23[n,i] = sum_j W3[n,j] * W2[j,i] ----
        int b2    = b - NCHUNK * COLT;
        int itile = b2 & 1;
        int chunk = b2 >> 1;
        int i  = itile * 256 + tid;
        int j0 = chunk * 137;
        int j1 = min(FUZZ, j0 + 137);

        float acc[NCLS];
#pragma unroll
        for (int n = 0; n < NCLS; n++) acc[n] = 0.f;
        for (int j = j0; j < j1; j++) {
            float w2 = __ldg(W2 + j * MID + i);
#pragma unroll
            for (int n = 0; n < NCLS; n++)
                acc[n] += __ldg(W3 + n * FUZZ + j) * w2;
        }
#pragma unroll
        for (int n = 0; n < NCLS; n++)
            g_partW[chunk * (NCLS * MID) + n * MID + i] = acc[n];
    }
}

// ============================================================
// Stage 2: reduce compact partials -> S (fixed order) + finalize W23.
//   chunk digit for f<5: chunk / {81,27,9,3,1}[f] % 3 must equal m.
//   f5: slot 5+m, all chunks.  f6: slot 8+m, all chunks.
// ============================================================
__global__ void k_reduceS() {
    int b = blockIdx.x, tid = threadIdx.x;
    if (b < 180) {
        int idx = b * 256 + tid;
        if (idx >= T21 * FUZZ) return;
        int t = idx / FUZZ, j = idx % FUZZ;
        int f = t / 3, m = t % 3;

        float s = 0.f;
        if (f < 5) {
            const int Dt[5] = {81, 27, 9, 3, 1};
            int D = Dt[f], n3D = 3 * D;
            for (int hi = 0; hi < NCHUNK / n3D; hi++)
                for (int lo = 0; lo < D; lo++) {
                    int c = hi * n3D + m * D + lo;
                    s += g_p[((size_t)c * NSLOT + f) * FUZZ + j];
                }
        } else {
            int slot = (f == 5) ? (5 + m) : (8 + m);
            const float* p = g_p + (size_t)slot * FUZZ + j;
#pragma unroll 3
            for (int c = 0; c < NCHUNK; c++)
                s += p[(size_t)c * NSLOT * FUZZ];
        }
        g_S[t * FUZZ + j] = s;
    } else {
        int e = (b - 180) * 256 + tid;
        if (e < NCLS * MID) {
            float s = 0.f;
#pragma unroll
            for (int c = 0; c < WCH; c++) s += g_partW[c * (NCLS * MID) + e];
            g_W23[e] = s;
        }
    }
}

// ============================================================
// Stage 3 (R7 verbatim): fold. V = W3 + W23*W1; per (n,jtile):
//   G/q/cc2 partials; last T21 blocks: rowS.
// ============================================================
__global__ void __launch_bounds__(256) k_fold(const float* __restrict__ W1,
                                              const float* __restrict__ W3,
                                              const float* __restrict__ b1,
                                              const float* __restrict__ b2,
                                              const float* __restrict__ b3) {
    int b = blockIdx.x, tid = threadIdx.x, lane = tid & 31, warp = tid >> 5;

    if (b < NCLS * COLT) {
        __shared__ float sW[MID];
        __shared__ float sV[256];
        int n = b / COLT, jt = b % COLT;

        for (int i = tid; i < MID; i += 256) sW[i] = g_W23[n * MID + i];
        __syncthreads();

        int j = jt * 256 + tid;
        bool jok = (j < FUZZ);
        int jj = jok ? j : (FUZZ - 1);

        float V = __ldg(W3 + n * FUZZ + jj);
        const float* wp = W1 + jj;
#pragma unroll 8
        for (int i = 0; i < MID; i++)
            V += sW[i] * __ldg(wp + (size_t)i * FUZZ);
        sV[tid] = jok ? V : 0.f;
        __syncthreads();

        float* dst = g_partF + (n * COLT + jt) * 24;
        int j0 = jt * 256;
        for (int t = warp; t < 24; t += 8) {
            float s = 0.f;
            if (t < T21) {
#pragma unroll
                for (int c = 0; c < 8; c++) {
                    int idx = c * 32 + lane;
                    int jx = j0 + idx;
                    float Sv = (jx < FUZZ) ? __ldg(&g_S[t * FUZZ + jx]) : 0.f;
                    s += sV[idx] * Sv;
                }
            } else if (t == 21) {
#pragma unroll
                for (int c = 0; c < 8; c++) s += sV[c * 32 + lane];
            } else if (t == 22) {
#pragma unroll
                for (int c = 0; c < 8; c++) {
                    int jx = j0 + c * 32 + lane;
                    if (jx < FUZZ)
                        s += __ldg(W3 + n * FUZZ + jx) * __ldg(b2 + jx);
                }
            } else {
                if (jt == 0) {
#pragma unroll
                    for (int c = 0; c < MID / 32; c++)
                        s += sW[c * 32 + lane] * __ldg(b1 + c * 32 + lane);
                }
            }
            for (int o = 16; o; o >>= 1)
                s += __shfl_down_sync(0xffffffffu, s, o);
            if (lane == 0) {
                if (t == 23 && jt == 0) s += __ldg(b3 + n);
                dst[t] = s;
            }
        }
    } else {
        __shared__ float sred[8];
        int t = b - NCLS * COLT;
        float s = 0.f;
        for (int j = tid; j < FUZZ; j += 256) s += g_S[t * FUZZ + j];
        for (int o = 16; o; o >>= 1)
            s += __shfl_down_sync(0xffffffffu, s, o);
        if (lane == 0) sred[warp] = s;
        __syncthreads();
        if (tid == 0) {
            float tot = 0.f;
#pragma unroll
            for (int w = 0; w < 8; w++) tot += sred[w];
            g_rowS[t] = tot;
        }
    }
}

// ============================================================
// Stage 4 (R7 verbatim): assemble partials, one thread per row
// ============================================================
__global__ void __launch_bounds__(256) k_main(
        const float* __restrict__ x,  const float* __restrict__ cc,
        const float* __restrict__ bb, const float* __restrict__ bais,
        float* __restrict__ out) {
    __shared__ float sG[NCLS * T21];
    __shared__ float sq[NCLS];
    __shared__ float scc[NCLS];
    __shared__ float srowS[T21];
    __shared__ float sc[T21];
    __shared__ float sib[T21];

    int tid = threadIdx.x;
    for (int e = tid; e < NCLS * T21; e += 256) {
        int n = e / T21, t = e % T21;
        float s = 0.f;
#pragma unroll
        for (int jt = 0; jt < COLT; jt++)
            s += g_partF[(n * COLT + jt) * 24 + t];
        sG[e] = s;
    }
    if (tid < NCLS) {
        float qq = 0.f, cv = 0.f;
#pragma unroll
        for (int jt = 0; jt < COLT; jt++) {
            qq += g_partF[(tid * COLT + jt) * 24 + 21];
            cv += g_partF[(tid * COLT + jt) * 24 + 22]
                + g_partF[(tid * COLT + jt) * 24 + 23];
        }
        sq[tid] = qq;
        scc[tid] = cv;
    }
    if (tid < T21) {
        srowS[tid] = g_rowS[tid];
        sc[tid] = __ldg(cc + tid);
        float bw = __ldg(bb + tid);
        sib[tid] = 1.0f / (bw * bw);
    }
    float bv = __ldg(bais);
    __syncthreads();

    int row = blockIdx.x * 256 + tid;
    float xv[N_FEAT];
#pragma unroll
    for (int f = 0; f < N_FEAT; f++) xv[f] = __ldg(x + row * N_FEAT + f);

    float u[T21];
    float rs = (float)FUZZ * bv;
#pragma unroll
    for (int t = 0; t < T21; t++) {
        float d = xv[t / 3] - sc[t];
        u[t] = expf(-d * d * sib[t]);
        rs += u[t] * srowS[t];
    }
    float inv = 1.0f / rs;

#pragma unroll
    for (int n = 0; n < NCLS; n++) {
        float s = bv * sq[n];
#pragma unroll
        for (int t = 0; t < T21; t++) s += u[t] * sG[n * T21 + t];
        float h = inv * s + scc[n];
        out[row * NCLS + n] = (h >= 0.f) ? h : 0.2f * h;
    }
}

// ============================================================
extern "C" void kernel_launch(void* const* d_in, const int* in_sizes, int n_in,
                              void* d_out, int out_size) {
    const float* x    = (const float*)d_in[0];
    const float* c    = (const float*)d_in[1];
    const float* b    = (const float*)d_in[2];
    const float* wei  = (const float*)d_in[3];
    const float* bais = (const float*)d_in[4];
    const float* W1   = (const float*)d_in[5];
    const float* b1   = (const float*)d_in[6];
    const float* W2   = (const float*)d_in[7];
    const float* b2   = (const float*)d_in[8];
    const float* W3   = (const float*)d_in[9];
    const float* b3   = (const float*)d_in[10];
    float* out = (float*)d_out;

    k_stage1<<<NCHUNK * COLT + 2 * WCH, 256>>>(wei, W2, W3);
    k_reduceS<<<200, 256>>>();
    k_fold<<<NCLS * COLT + T21, 256>>>(W1, W3, b1, b2, b3);
    k_main<<<BATCH / 256, 256>>>(x, c, b, bais, out);
}

// round 11
// speedup vs baseline: 2.8804x; 1.5670x over previous
#include <cuda_runtime.h>
#include <math.h>

#define N_FEAT 7
#define FUZZ   2187
#define MID    512
#define NCLS   10
#define BATCH  4096
#define T21    21
#define NCHUNK 81            // chunks of 27 k
#define CHUNK_K 27
#define COLT   9             // 256-wide column tiles
#define WCH    16            // j-chunks for W23 partials
#define SN     (T21 * FUZZ)  // 45927 elements of S

// ---- device scratch (no allocations allowed) ----
__device__ float g_S[SN];
__device__ float g_rowS[T21];
__device__ float g_partW[WCH * NCLS * MID];
__device__ float g_partF[NCLS * COLT * 24];

// ============================================================
// Zero S (split into 3 launches so stage1 sits at launch #4,
// which is the position ncu captures).
// ============================================================
__global__ void k_zero(int ofs) {
    int i = ofs + blockIdx.x * 1024 + threadIdx.x;
    if (i < SN) g_S[i] = 0.f;
}

// ============================================================
// Stage 1: digit-factorized wei reduction, accumulated straight
// into L2-resident g_S via REDG (no partials, no reduce pass).
//   k = chunk*27 + kk:
//     f=0..3: digit = chunk/{27,9,3,1} % 3  (block-constant)
//     f=4: kk/9, f=5: (kk/3)%3, f=6: kk%3
//   + 32 tail blocks: W23 partials.
// ============================================================
__global__ void __launch_bounds__(256) k_stage1(
        const float* __restrict__ wei,
        const float* __restrict__ W2,
        const float* __restrict__ W3) {
    int b   = blockIdx.x;
    int tid = threadIdx.x;

    if (b < NCHUNK * COLT) {
        int colTile = b % COLT;
        int chunk   = b / COLT;
        int j  = colTile * 256 + tid;
        bool ok = (j < FUZZ);
        int jj = ok ? j : 0;

        float a0 = 0.f, a1 = 0.f, a2 = 0.f, a3 = 0.f;
        float a4[3] = {0.f, 0.f, 0.f};
        float a5[3] = {0.f, 0.f, 0.f};
        float a6[3] = {0.f, 0.f, 0.f};

        const float* base = wei + (size_t)chunk * CHUNK_K * 7 * FUZZ + jj;
#pragma unroll 3
        for (int kk = 0; kk < CHUNK_K; kk++) {
            const float* rp = base + (size_t)kk * 7 * FUZZ;
            a0 += __ldg(rp);
            a1 += __ldg(rp + 1 * FUZZ);
            a2 += __ldg(rp + 2 * FUZZ);
            a3 += __ldg(rp + 3 * FUZZ);
            float v4 = __ldg(rp + 4 * FUZZ);
            float v5 = __ldg(rp + 5 * FUZZ);
            float v6 = __ldg(rp + 6 * FUZZ);
            int m4 = kk / 9, m5 = (kk / 3) % 3, m6 = kk % 3;
            a4[0] += (m4 == 0) ? v4 : 0.f;
            a4[1] += (m4 == 1) ? v4 : 0.f;
            a4[2] += (m4 == 2) ? v4 : 0.f;
            a5[0] += (m5 == 0) ? v5 : 0.f;
            a5[1] += (m5 == 1) ? v5 : 0.f;
            a5[2] += (m5 == 2) ? v5 : 0.f;
            a6[0] += (m6 == 0) ? v6 : 0.f;
            a6[1] += (m6 == 1) ? v6 : 0.f;
            a6[2] += (m6 == 2) ? v6 : 0.f;
        }
        if (ok) {
            int t0 = 0 * 3 + (chunk / 27) % 3;
            int t1 = 1 * 3 + (chunk / 9) % 3;
            int t2 = 2 * 3 + (chunk / 3) % 3;
            int t3 = 3 * 3 + chunk % 3;
            atomicAdd(&g_S[t0 * FUZZ + j], a0);
            atomicAdd(&g_S[t1 * FUZZ + j], a1);
            atomicAdd(&g_S[t2 * FUZZ + j], a2);
            atomicAdd(&g_S[t3 * FUZZ + j], a3);
#pragma unroll
            for (int m = 0; m < 3; m++) {
                atomicAdd(&g_S[(12 + m) * FUZZ + j], a4[m]);
                atomicAdd(&g_S[(15 + m) * FUZZ + j], a5[m]);
                atomicAdd(&g_S[(18 + m) * FUZZ + j], a6[m]);
            }
        }
    } else {
        // ---- W23 partial: W23[n,i] = sum_j W3[n,j] * W2[j,i] ----
        int b2    = b - NCHUNK * COLT;
        int itile = b2 & 1;
        int chunk = b2 >> 1;
        int i  = itile * 256 + tid;
        int j0 = chunk * 137;
        int j1 = min(FUZZ, j0 + 137);

        float acc[NCLS];
#pragma unroll
        for (int n = 0; n < NCLS; n++) acc[n] = 0.f;
        for (int j = j0; j < j1; j++) {
            float w2 = __ldg(W2 + j * MID + i);
#pragma unroll
            for (int n = 0; n < NCLS; n++)
                acc[n] += __ldg(W3 + n * FUZZ + j) * w2;
        }
#pragma unroll
        for (int n = 0; n < NCLS; n++)
            g_partW[chunk * (NCLS * MID) + n * MID + i] = acc[n];
    }
}

// ============================================================
// Stage 2: fold. W23 reduced inline into smem; V = W3 + W23*W1;
//   per (n,jtile): G/q/cc2 partials; last T21 blocks: rowS.
// ============================================================
__global__ void __launch_bounds__(256) k_fold(const float* __restrict__ W1,
                                              const float* __restrict__ W3,
                                              const float* __restrict__ b1,
                                              const float* __restrict__ b2,
                                              const float* __restrict__ b3) {
    int b = blockIdx.x, tid = threadIdx.x, lane = tid & 31, warp = tid >> 5;

    if (b < NCLS * COLT) {
        __shared__ float sW[MID];
        __shared__ float sV[256];
        int n = b / COLT, jt = b % COLT;

        // inline W23 finalize: sum the 16 partial chunks
        for (int i = tid; i < MID; i += 256) {
            float s = 0.f;
#pragma unroll
            for (int c = 0; c < WCH; c++)
                s += g_partW[c * (NCLS * MID) + n * MID + i];
            sW[i] = s;
        }
        __syncthreads();

        int j = jt * 256 + tid;
        bool jok = (j < FUZZ);
        int jj = jok ? j : (FUZZ - 1);

        float V = __ldg(W3 + n * FUZZ + jj);
        const float* wp = W1 + jj;
#pragma unroll 8
        for (int i = 0; i < MID; i++)
            V += sW[i] * __ldg(wp + (size_t)i * FUZZ);
        sV[tid] = jok ? V : 0.f;
        __syncthreads();

        float* dst = g_partF + (n * COLT + jt) * 24;
        int j0 = jt * 256;
        for (int t = warp; t < 24; t += 8) {
            float s = 0.f;
            if (t < T21) {
#pragma unroll
                for (int c = 0; c < 8; c++) {
                    int idx = c * 32 + lane;
                    int jx = j0 + idx;
                    float Sv = (jx < FUZZ) ? __ldg(&g_S[t * FUZZ + jx]) : 0.f;
                    s += sV[idx] * Sv;
                }
            } else if (t == 21) {
#pragma unroll
                for (int c = 0; c < 8; c++) s += sV[c * 32 + lane];
            } else if (t == 22) {
#pragma unroll
                for (int c = 0; c < 8; c++) {
                    int jx = j0 + c * 32 + lane;
                    if (jx < FUZZ)
                        s += __ldg(W3 + n * FUZZ + jx) * __ldg(b2 + jx);
                }
            } else { // t == 23: only jt==0 adds b3 + W23.b1
                if (jt == 0) {
#pragma unroll
                    for (int c = 0; c < MID / 32; c++)
                        s += sW[c * 32 + lane] * __ldg(b1 + c * 32 + lane);
                }
            }
            for (int o = 16; o; o >>= 1)
                s += __shfl_down_sync(0xffffffffu, s, o);
            if (lane == 0) {
                if (t == 23 && jt == 0) s += __ldg(b3 + n);
                dst[t] = s;
            }
        }
    } else {
        __shared__ float sred[8];
        int t = b - NCLS * COLT;
        float s = 0.f;
        for (int j = tid; j < FUZZ; j += 256) s += g_S[t * FUZZ + j];
        for (int o = 16; o; o >>= 1)
            s += __shfl_down_sync(0xffffffffu, s, o);
        if (lane == 0) sred[warp] = s;
        __syncthreads();
        if (tid == 0) {
            float tot = 0.f;
#pragma unroll
            for (int w = 0; w < 8; w++) tot += sred[w];
            g_rowS[t] = tot;
        }
    }
}

// ============================================================
// Stage 3: assemble partials, one thread per batch row
// ============================================================
__global__ void __launch_bounds__(256) k_main(
        const float* __restrict__ x,  const float* __restrict__ cc,
        const float* __restrict__ bb, const float* __restrict__ bais,
        float* __restrict__ out) {
    __shared__ float sG[NCLS * T21];
    __shared__ float sq[NCLS];
    __shared__ float scc[NCLS];
    __shared__ float srowS[T21];
    __shared__ float sc[T21];
    __shared__ float sib[T21];

    int tid = threadIdx.x;
    for (int e = tid; e < NCLS * T21; e += 256) {
        int n = e / T21, t = e % T21;
        float s = 0.f;
#pragma unroll
        for (int jt = 0; jt < COLT; jt++)
            s += g_partF[(n * COLT + jt) * 24 + t];
        sG[e] = s;
    }
    if (tid < NCLS) {
        float qq = 0.f, cv = 0.f;
#pragma unroll
        for (int jt = 0; jt < COLT; jt++) {
            qq += g_partF[(tid * COLT + jt) * 24 + 21];
            cv += g_partF[(tid * COLT + jt) * 24 + 22]
                + g_partF[(tid * COLT + jt) * 24 + 23];
        }
        sq[tid] = qq;
        scc[tid] = cv;
    }
    if (tid < T21) {
        srowS[tid] = g_rowS[tid];
        sc[tid] = __ldg(cc + tid);
        float bw = __ldg(bb + tid);
        sib[tid] = 1.0f / (bw * bw);
    }
    float bv = __ldg(bais);
    __syncthreads();

    int row = blockIdx.x * 256 + tid;
    float xv[N_FEAT];
#pragma unroll
    for (int f = 0; f < N_FEAT; f++) xv[f] = __ldg(x + row * N_FEAT + f);

    float u[T21];
    float rs = (float)FUZZ * bv;
#pragma unroll
    for (int t = 0; t < T21; t++) {
        float d = xv[t / 3] - sc[t];
        u[t] = expf(-d * d * sib[t]);
        rs += u[t] * srowS[t];
    }
    float inv = 1.0f / rs;

#pragma unroll
    for (int n = 0; n < NCLS; n++) {
        float s = bv * sq[n];
#pragma unroll
        for (int t = 0; t < T21; t++) s += u[t] * sG[n * T21 + t];
        float h = inv * s + scc[n];
        out[row * NCLS + n] = (h >= 0.f) ? h : 0.2f * h;
    }
}

// ============================================================
extern "C" void kernel_launch(void* const* d_in, const int* in_sizes, int n_in,
                              void* d_out, int out_size) {
    const float* x    = (const float*)d_in[0];
    const float* c    = (const float*)d_in[1];
    const float* b    = (const float*)d_in[2];
    const float* wei  = (const float*)d_in[3];
    const float* bais = (const float*)d_in[4];
    const float* W1   = (const float*)d_in[5];
    const float* b1   = (const float*)d_in[6];
    const float* W2   = (const float*)d_in[7];
    const float* b2   = (const float*)d_in[8];
    const float* W3   = (const float*)d_in[9];
    const float* b3   = (const float*)d_in[10];
    float* out = (float*)d_out;

    // zero S in 3 tiny launches so stage1 is launch #4 (profiled slot)
    k_zero<<<15, 1024>>>(0);                 // pos 1
    k_zero<<<15, 1024>>>(15 * 1024);         // pos 2
    k_zero<<<15, 1024>>>(30 * 1024);         // pos 3
    k_stage1<<<NCHUNK * COLT + 2 * WCH, 256>>>(wei, W2, W3);  // pos 4 <- ncu
    k_fold<<<NCLS * COLT + T21, 256>>>(W1, W3, b1, b2, b3);   // pos 5
    k_main<<<BATCH / 256, 256>>>(x, c, b, bais, out);         // pos 6
}

// round 12
// speedup vs baseline: 2.9876x; 1.0372x over previous
#include <cuda_runtime.h>
#include <math.h>

#define N_FEAT 7
#define FUZZ   2187
#define MID    512
#define NCLS   10
#define BATCH  4096
#define T21    21
#define NCHUNK 81            // chunks of 27 k
#define CHUNK_K 27
#define CT5    5             // 512-wide column tiles
#define WCH    16            // j-chunks for W23 partials
#define SN     (T21 * FUZZ)  // 45927
#define VN     (NCLS * FUZZ) // 21870
#define ZTOT   (SN + VN)     // 67797

// ---- device scratch (no allocations allowed) ----
__device__ float g_S[SN];
__device__ float g_V[VN];
__device__ float g_rowS[T21];
__device__ float g_partW[WCH * NCLS * MID];
__device__ float g_G[NCLS * T21];
__device__ float g_q[NCLS];
__device__ float g_cc2[NCLS];

// ============================================================
// Zero S and V (3 launches so stage1 sits at profiled pos 4)
// ============================================================
__global__ void k_zero(int ofs) {
    int i = ofs + blockIdx.x * 1024 + threadIdx.x;
    if (i < SN) g_S[i] = 0.f;
    else if (i < ZTOT) g_V[i - SN] = 0.f;
}

// ============================================================
// Stage 1: digit-factorized wei reduction -> atomic g_S.
//   Each thread owns TWO j columns (512-wide tiles) for 2x MLP.
//   + 32 tail blocks: W23 partials.
// ============================================================
__global__ void __launch_bounds__(256) k_stage1(
        const float* __restrict__ wei,
        const float* __restrict__ W2,
        const float* __restrict__ W3) {
    int b   = blockIdx.x;
    int tid = threadIdx.x;

    if (b < NCHUNK * CT5) {
        int colTile = b % CT5;
        int chunk   = b / CT5;
        int jA = colTile * 512 + tid;
        int jB = jA + 256;
        bool okA = (jA < FUZZ), okB = (jB < FUZZ);
        int ja = okA ? jA : 0, jb = okB ? jB : 0;

        float aA[13], aB[13];
#pragma unroll
        for (int s = 0; s < 13; s++) { aA[s] = 0.f; aB[s] = 0.f; }

        const float* base = wei + (size_t)chunk * CHUNK_K * 7 * FUZZ;
#pragma unroll 3
        for (int kk = 0; kk < CHUNK_K; kk++) {
            const float* rp = base + (size_t)kk * 7 * FUZZ;
            int m4 = kk / 9, m5 = (kk / 3) % 3, m6 = kk % 3;
#pragma unroll
            for (int f = 0; f < 4; f++) {
                aA[f] += __ldg(rp + f * FUZZ + ja);
                aB[f] += __ldg(rp + f * FUZZ + jb);
            }
            float v4A = __ldg(rp + 4 * FUZZ + ja), v4B = __ldg(rp + 4 * FUZZ + jb);
            float v5A = __ldg(rp + 5 * FUZZ + ja), v5B = __ldg(rp + 5 * FUZZ + jb);
            float v6A = __ldg(rp + 6 * FUZZ + ja), v6B = __ldg(rp + 6 * FUZZ + jb);
#pragma unroll
            for (int m = 0; m < 3; m++) {
                aA[4 + m]  += (m4 == m) ? v4A : 0.f;
                aB[4 + m]  += (m4 == m) ? v4B : 0.f;
                aA[7 + m]  += (m5 == m) ? v5A : 0.f;
                aB[7 + m]  += (m5 == m) ? v5B : 0.f;
                aA[10 + m] += (m6 == m) ? v6A : 0.f;
                aB[10 + m] += (m6 == m) ? v6B : 0.f;
            }
        }

        int t0 = (chunk / 27) % 3;
        int t1 = (chunk / 9) % 3;
        int t2 = (chunk / 3) % 3;
        int t3 = chunk % 3;
        if (okA) {
            atomicAdd(&g_S[(0 + t0) * FUZZ + jA], aA[0]);
            atomicAdd(&g_S[(3 + t1) * FUZZ + jA], aA[1]);
            atomicAdd(&g_S[(6 + t2) * FUZZ + jA], aA[2]);
            atomicAdd(&g_S[(9 + t3) * FUZZ + jA], aA[3]);
#pragma unroll
            for (int m = 0; m < 3; m++) {
                atomicAdd(&g_S[(12 + m) * FUZZ + jA], aA[4 + m]);
                atomicAdd(&g_S[(15 + m) * FUZZ + jA], aA[7 + m]);
                atomicAdd(&g_S[(18 + m) * FUZZ + jA], aA[10 + m]);
            }
        }
        if (okB) {
            atomicAdd(&g_S[(0 + t0) * FUZZ + jB], aB[0]);
            atomicAdd(&g_S[(3 + t1) * FUZZ + jB], aB[1]);
            atomicAdd(&g_S[(6 + t2) * FUZZ + jB], aB[2]);
            atomicAdd(&g_S[(9 + t3) * FUZZ + jB], aB[3]);
#pragma unroll
            for (int m = 0; m < 3; m++) {
                atomicAdd(&g_S[(12 + m) * FUZZ + jB], aB[4 + m]);
                atomicAdd(&g_S[(15 + m) * FUZZ + jB], aB[7 + m]);
                atomicAdd(&g_S[(18 + m) * FUZZ + jB], aB[10 + m]);
            }
        }
    } else {
        // ---- W23 partial: W23[n,i] = sum_j W3[n,j] * W2[j,i] ----
        int b2    = b - NCHUNK * CT5;
        int itile = b2 & 1;
        int chunk = b2 >> 1;
        int i  = itile * 256 + tid;
        int j0 = chunk * 137;
        int j1 = min(FUZZ, j0 + 137);

        float acc[NCLS];
#pragma unroll
        for (int n = 0; n < NCLS; n++) acc[n] = 0.f;
        for (int j = j0; j < j1; j++) {
            float w2 = __ldg(W2 + j * MID + i);
#pragma unroll
            for (int n = 0; n < NCLS; n++)
                acc[n] += __ldg(W3 + n * FUZZ + j) * w2;
        }
#pragma unroll
        for (int n = 0; n < NCLS; n++)
            g_partW[chunk * (NCLS * MID) + n * MID + i] = acc[n];
    }
}

// ============================================================
// Stage 2: V[n,j] = W3[n,j] + sum_i W23[n,i] W1[i,j]
//   36 blocks = 9 j-tiles x 4 i-slices; all 10 n per W1 read.
// ============================================================
__global__ void __launch_bounds__(256) k_foldV(const float* __restrict__ W1,
                                               const float* __restrict__ W3) {
    __shared__ float sW[NCLS * 128];
    int b = blockIdx.x, tid = threadIdx.x;
    int jt = b % 9, isl = b / 9;
    int i0 = isl * 128;

    for (int e = tid; e < NCLS * 128; e += 256) {
        int n = e / 128, il = e % 128;
        float s = 0.f;
#pragma unroll
        for (int c = 0; c < WCH; c++)
            s += g_partW[c * (NCLS * MID) + n * MID + i0 + il];
        sW[e] = s;
    }
    __syncthreads();

    int j = jt * 256 + tid;
    bool ok = (j < FUZZ);
    int jj = ok ? j : 0;

    float V[NCLS];
#pragma unroll
    for (int n = 0; n < NCLS; n++) V[n] = 0.f;

#pragma unroll 4
    for (int il = 0; il < 128; il++) {
        float w1 = __ldg(W1 + (size_t)(i0 + il) * FUZZ + jj);
#pragma unroll
        for (int n = 0; n < NCLS; n++)
            V[n] += sW[n * 128 + il] * w1;
    }
    if (ok) {
#pragma unroll
        for (int n = 0; n < NCLS; n++) {
            float add = V[n] + ((isl == 0) ? __ldg(W3 + n * FUZZ + j) : 0.f);
            atomicAdd(&g_V[n * FUZZ + j], add);
        }
    }
}

// ============================================================
// Stage 3: contract. G[n,t] = V[n].S[t]; q[n] = sum V[n];
//   cc2[n] = W3[n].b2 + b3[n] + W23[n].b1; rowS[t] = sum S[t].
// ============================================================
__global__ void __launch_bounds__(256) k_contract(const float* __restrict__ W3,
                                                  const float* __restrict__ b1,
                                                  const float* __restrict__ b2,
                                                  const float* __restrict__ b3) {
    int lane = threadIdx.x & 31;
    int gw   = blockIdx.x * 8 + (threadIdx.x >> 5);

    float s = 0.f;
    if (gw < NCLS * T21) {
        int n = gw / T21, t = gw % T21;
        const float* Vp = g_V + n * FUZZ;
        const float* Sp = g_S + t * FUZZ;
        for (int j = lane; j < FUZZ; j += 32)
            s += Vp[j] * Sp[j];
        for (int o = 16; o; o >>= 1) s += __shfl_down_sync(0xffffffffu, s, o);
        if (lane == 0) g_G[gw] = s;
    } else if (gw < NCLS * T21 + NCLS) {
        int n = gw - NCLS * T21;
        const float* Vp = g_V + n * FUZZ;
        for (int j = lane; j < FUZZ; j += 32) s += Vp[j];
        for (int o = 16; o; o >>= 1) s += __shfl_down_sync(0xffffffffu, s, o);
        if (lane == 0) g_q[n] = s;
    } else if (gw < NCLS * T21 + 2 * NCLS) {
        int n = gw - NCLS * T21 - NCLS;
        for (int j = lane; j < FUZZ; j += 32)
            s += __ldg(W3 + n * FUZZ + j) * __ldg(b2 + j);
        for (int e = lane; e < WCH * MID; e += 32) {
            int c = e / MID, i = e % MID;
            s += g_partW[c * (NCLS * MID) + n * MID + i] * __ldg(b1 + i);
        }
        for (int o = 16; o; o >>= 1) s += __shfl_down_sync(0xffffffffu, s, o);
        if (lane == 0) g_cc2[n] = s + __ldg(b3 + n);
    } else if (gw < NCLS * T21 + 2 * NCLS + T21) {
        int t = gw - NCLS * T21 - 2 * NCLS;
        const float* Sp = g_S + t * FUZZ;
        for (int j = lane; j < FUZZ; j += 32) s += Sp[j];
        for (int o = 16; o; o >>= 1) s += __shfl_down_sync(0xffffffffu, s, o);
        if (lane == 0) g_rowS[t] = s;
    }
}

// ============================================================
// Stage 4: one thread per batch row (~250 FMA + 21 exp each)
// ============================================================
__global__ void __launch_bounds__(256) k_main(
        const float* __restrict__ x,  const float* __restrict__ cc,
        const float* __restrict__ bb, const float* __restrict__ bais,
        float* __restrict__ out) {
    __shared__ float sG[NCLS * T21];
    __shared__ float sq[NCLS];
    __shared__ float scc[NCLS];
    __shared__ float srowS[T21];
    __shared__ float sc[T21];
    __shared__ float sib[T21];

    int tid = threadIdx.x;
    for (int e = tid; e < NCLS * T21; e += 256) sG[e] = g_G[e];
    if (tid < NCLS) { sq[tid] = g_q[tid]; scc[tid] = g_cc2[tid]; }
    if (tid < T21) {
        srowS[tid] = g_rowS[tid];
        sc[tid] = __ldg(cc + tid);
        float bw = __ldg(bb + tid);
        sib[tid] = 1.0f / (bw * bw);
    }
    float bv = __ldg(bais);
    __syncthreads();

    int row = blockIdx.x * 256 + tid;
    float xv[N_FEAT];
#pragma unroll
    for (int f = 0; f < N_FEAT; f++) xv[f] = __ldg(x + row * N_FEAT + f);

    float u[T21];
    float rs = (float)FUZZ * bv;
#pragma unroll
    for (int t = 0; t < T21; t++) {
        float d = xv[t / 3] - sc[t];
        u[t] = expf(-d * d * sib[t]);
        rs += u[t] * srowS[t];
    }
    float inv = 1.0f / rs;

#pragma unroll
    for (int n = 0; n < NCLS; n++) {
        float s = bv * sq[n];
#pragma unroll
        for (int t = 0; t < T21; t++) s += u[t] * sG[n * T21 + t];
        float h = inv * s + scc[n];
        out[row * NCLS + n] = (h >= 0.f) ? h : 0.2f * h;
    }
}

// ============================================================
extern "C" void kernel_launch(void* const* d_in, const int* in_sizes, int n_in,
                              void* d_out, int out_size) {
    const float* x    = (const float*)d_in[0];
    const float* c    = (const float*)d_in[1];
    const float* b    = (const float*)d_in[2];
    const float* wei  = (const float*)d_in[3];
    const float* bais = (const float*)d_in[4];
    const float* W1   = (const float*)d_in[5];
    const float* b1   = (const float*)d_in[6];
    const float* W2   = (const float*)d_in[7];
    const float* b2   = (const float*)d_in[8];
    const float* W3   = (const float*)d_in[9];
    const float* b3   = (const float*)d_in[10];
    float* out = (float*)d_out;

    k_zero<<<23, 1024>>>(0);                                  // pos 1
    k_zero<<<23, 1024>>>(23 * 1024);                          // pos 2
    k_zero<<<23, 1024>>>(46 * 1024);                          // pos 3
    k_stage1<<<NCHUNK * CT5 + 2 * WCH, 256>>>(wei, W2, W3);   // pos 4 <- ncu
    k_foldV<<<36, 256>>>(W1, W3);                             // pos 5
    k_contract<<<33, 256>>>(W3, b1, b2, b3);                  // pos 6
    k_main<<<BATCH / 256, 256>>>(x, c, b, bais, out);         // pos 7
}